// round 1
// baseline (speedup 1.0000x reference)
#include <cuda_runtime.h>
#include <stdint.h>

#define THREADS 256
#define GRID    2368
#define CUTBITS 0x40000000u   /* bit pattern of 2.0f: values below only counted */

__device__ unsigned           g_hist1[1024];     // coarse bins [1024, 2048)
__device__ unsigned           g_histlo[2048];    // fallback full coarse hist
__device__ unsigned           g_hist2[1u << 20]; // fine hist (low 20 bits)
__device__ unsigned           g_part[1024];      // chunk partial sums for fine hist
__device__ unsigned long long g_zeros;
__device__ unsigned long long g_below;
__device__ int                g_need;            // fallback needed?
__device__ long long          g_idx;
__device__ int                g_bin;             // target coarse bin
__device__ long long          g_rank;            // rank within coarse bin
__device__ float              g_th;
__device__ float              g_step;

__global__ void initk() {
    unsigned t = blockIdx.x * blockDim.x + threadIdx.x;
    unsigned T = gridDim.x * blockDim.x;
    for (unsigned i = t; i < (1u << 20); i += T) g_hist2[i] = 0u;
    for (unsigned i = t; i < 2048u; i += T) g_histlo[i] = 0u;
    for (unsigned i = t; i < 1024u; i += T) g_hist1[i] = 0u;
    if (t == 0) { g_zeros = 0ull; g_below = 0ull; g_need = 0; }
}

// ---------------- Pass 1: coarse histogram (only |x| >= 2.0), count below + zeros
__global__ void __launch_bounds__(THREADS) pass1(const float4* __restrict__ x4,
                                                 int n4, int n) {
    __shared__ unsigned sh[4][1024];
    int tid = threadIdx.x;
    for (int i = tid; i < 4096; i += THREADS) ((unsigned*)sh)[i] = 0u;
    __syncthreads();
    unsigned* hh = sh[tid >> 6];

    unsigned below = 0u, zeros = 0u;
    int stride = gridDim.x * blockDim.x;

#define P1_PROC(f) do { \
        unsigned u = __float_as_uint(f) & 0x7fffffffu; \
        if (u < CUTBITS) { below += 1u; zeros += (u == 0u) ? 1u : 0u; } \
        else atomicAdd(&hh[(u >> 20) - 1024u], 1u); \
    } while (0)

    for (int i = blockIdx.x * blockDim.x + tid; i < n4; i += stride) {
        float4 v = x4[i];
        P1_PROC(v.x); P1_PROC(v.y); P1_PROC(v.z); P1_PROC(v.w);
    }
    int rem = n - (n4 << 2);
    if (blockIdx.x == 0 && tid < rem) {
        float f = ((const float*)x4)[(n4 << 2) + tid];
        P1_PROC(f);
    }
#undef P1_PROC

    // warp reduce counters, one atomic per warp
    for (int o = 16; o; o >>= 1) {
        below += __shfl_down_sync(0xffffffffu, below, o);
        zeros += __shfl_down_sync(0xffffffffu, zeros, o);
    }
    if ((tid & 31) == 0) {
        if (below) atomicAdd(&g_below, (unsigned long long)below);
        if (zeros) atomicAdd(&g_zeros, (unsigned long long)zeros);
    }
    __syncthreads();
    for (int b = tid; b < 1024; b += THREADS) {
        unsigned s = sh[0][b] + sh[1][b] + sh[2][b] + sh[3][b];
        if (s) atomicAdd(&g_hist1[b], s);
    }
}

__device__ __forceinline__ unsigned block_scan_1024(unsigned* s, unsigned v, int t) {
    s[t] = v;
    __syncthreads();
    for (int off = 1; off < 1024; off <<= 1) {
        unsigned u = (t >= off) ? s[t - off] : 0u;
        __syncthreads();
        s[t] += u;
        __syncthreads();
    }
    return s[t];
}

// ---------------- Scan 1: compute idx, locate coarse bin (fast path)
__global__ void scan1a(long long n) {
    __shared__ unsigned s[1024];
    int t = threadIdx.x;
    long long zeros = (long long)g_zeros;
    long long below = (long long)g_below;
    long long nnz = n - zeros;
    long long idx = (long long)floorf(0.997f * (float)nnz) + (n - nnz);
    if (idx > n - 1) idx = n - 1;
    if (idx < 0) idx = 0;
    int need = (below > idx) ? 1 : 0;
    if (t == 0) { g_need = need; g_idx = idx; }
    if (need) return;

    unsigned c = g_hist1[t];
    unsigned incl = block_scan_1024(s, c, t);
    long long r = idx - below;
    long long inclL = (long long)incl;
    long long exclL = inclL - (long long)c;
    if (r >= exclL && r < inclL) {
        g_bin = 1024 + t;
        g_rank = r - exclL;
    }
}

// ---------------- Pass 1b (fallback only): full coarse histogram
__global__ void __launch_bounds__(THREADS) pass1b(const float4* __restrict__ x4,
                                                  int n4, int n) {
    if (!g_need) return;
    __shared__ unsigned sh[4][2048];
    int tid = threadIdx.x;
    for (int i = tid; i < 8192; i += THREADS) ((unsigned*)sh)[i] = 0u;
    __syncthreads();
    unsigned* hh = sh[tid >> 6];
    int stride = gridDim.x * blockDim.x;
#define P1B_PROC(f) do { \
        unsigned u = __float_as_uint(f) & 0x7fffffffu; \
        atomicAdd(&hh[u >> 20], 1u); \
    } while (0)
    for (int i = blockIdx.x * blockDim.x + tid; i < n4; i += stride) {
        float4 v = x4[i];
        P1B_PROC(v.x); P1B_PROC(v.y); P1B_PROC(v.z); P1B_PROC(v.w);
    }
    int rem = n - (n4 << 2);
    if (blockIdx.x == 0 && tid < rem) {
        float f = ((const float*)x4)[(n4 << 2) + tid];
        P1B_PROC(f);
    }
#undef P1B_PROC
    __syncthreads();
    for (int b = tid; b < 2048; b += THREADS) {
        unsigned s = sh[0][b] + sh[1][b] + sh[2][b] + sh[3][b];
        if (s) atomicAdd(&g_histlo[b], s);
    }
}

// ---------------- Scan 1b (fallback only): locate coarse bin over full hist
__global__ void scan1b() {
    if (!g_need) return;
    __shared__ unsigned s[1024];
    int t = threadIdx.x;
    unsigned c0 = g_histlo[2 * t];
    unsigned c1 = g_histlo[2 * t + 1];
    unsigned incl = block_scan_1024(s, c0 + c1, t);
    long long r = g_idx;
    long long inclL = (long long)incl;
    long long exclL = inclL - (long long)(c0 + c1);
    if (r >= exclL && r < inclL) {
        if (r < exclL + (long long)c0) { g_bin = 2 * t;     g_rank = r - exclL; }
        else                           { g_bin = 2 * t + 1; g_rank = r - exclL - (long long)c0; }
    }
}

// ---------------- Pass 2: fine histogram of target coarse bin (low 20 bits)
__global__ void __launch_bounds__(THREADS) pass2(const float4* __restrict__ x4,
                                                 int n4, int n) {
    int tid = threadIdx.x;
    unsigned bin = (unsigned)g_bin;
    int stride = gridDim.x * blockDim.x;
#define P2_PROC(f) do { \
        unsigned u = __float_as_uint(f) & 0x7fffffffu; \
        if ((u >> 20) == bin) atomicAdd(&g_hist2[u & 0xFFFFFu], 1u); \
    } while (0)
    for (int i = blockIdx.x * blockDim.x + tid; i < n4; i += stride) {
        float4 v = x4[i];
        P2_PROC(v.x); P2_PROC(v.y); P2_PROC(v.z); P2_PROC(v.w);
    }
    int rem = n - (n4 << 2);
    if (blockIdx.x == 0 && tid < rem) {
        float f = ((const float*)x4)[(n4 << 2) + tid];
        P2_PROC(f);
    }
#undef P2_PROC
}

// ---------------- Scan 2a: per-chunk partial sums of fine hist
__global__ void __launch_bounds__(THREADS) scan2a() {
    __shared__ unsigned red[THREADS / 32];
    int b = blockIdx.x;          // 1024 chunks of 1024 bins
    int tid = threadIdx.x;
    unsigned sum = 0u;
    for (int i = tid; i < 1024; i += THREADS) sum += g_hist2[b * 1024 + i];
    for (int o = 16; o; o >>= 1) sum += __shfl_down_sync(0xffffffffu, sum, o);
    if ((tid & 31) == 0) red[tid >> 5] = sum;
    __syncthreads();
    if (tid == 0) {
        unsigned tot = 0u;
        for (int w = 0; w < THREADS / 32; w++) tot += red[w];
        g_part[b] = tot;
    }
}

// ---------------- Scan 2b: locate exact fine bin -> th, step
__global__ void scan2b() {
    __shared__ unsigned s[1024];
    __shared__ int sc;
    __shared__ long long sr;
    int t = threadIdx.x;
    unsigned c = g_part[t];
    unsigned incl = block_scan_1024(s, c, t);
    long long r = g_rank;
    long long inclL = (long long)incl;
    long long exclL = inclL - (long long)c;
    if (r >= exclL && r < inclL) { sc = t; sr = r - exclL; }
    __syncthreads();
    int chunk = sc;
    long long r2 = sr;
    unsigned c2 = g_hist2[(unsigned)chunk * 1024u + (unsigned)t];
    __syncthreads();
    unsigned incl2 = block_scan_1024(s, c2, t);
    long long incl2L = (long long)incl2;
    long long excl2L = incl2L - (long long)c2;
    if (r2 >= excl2L && r2 < incl2L) {
        unsigned bits = ((unsigned)g_bin << 20) | ((unsigned)chunk * 1024u + (unsigned)t);
        float th = __uint_as_float(bits);
        g_th = th;
        g_step = th / 7.0f;    // n_lv_pos = 2^(4-1)-1 = 7
    }
}

// ---------------- Pass 3: quantize
__device__ __forceinline__ float quant1(float v, float th, float step) {
    if (fabsf(v) <= th) return rintf(v / step) * step;  // IEEE div + round-half-even (matches XLA)
    return v;
}

__global__ void __launch_bounds__(THREADS) pass3(const float4* __restrict__ x4,
                                                 float4* __restrict__ o4,
                                                 int n4, int n) {
    int tid = threadIdx.x;
    float th = g_th;
    float step = g_step;
    bool doq = (th > 0.0f);
    int stride = gridDim.x * blockDim.x;
    for (int i = blockIdx.x * blockDim.x + tid; i < n4; i += stride) {
        float4 v = x4[i];
        if (doq) {
            v.x = quant1(v.x, th, step);
            v.y = quant1(v.y, th, step);
            v.z = quant1(v.z, th, step);
            v.w = quant1(v.w, th, step);
        }
        o4[i] = v;
    }
    int rem = n - (n4 << 2);
    if (blockIdx.x == 0 && tid < rem) {
        int i = (n4 << 2) + tid;
        float f = ((const float*)x4)[i];
        ((float*)o4)[i] = doq ? quant1(f, th, step) : f;
    }
}

extern "C" void kernel_launch(void* const* d_in, const int* in_sizes, int n_in,
                              void* d_out, int out_size) {
    const float* x = (const float*)d_in[0];
    int n = in_sizes[0];
    int n4 = n >> 2;

    initk<<<1024, THREADS>>>();
    pass1<<<GRID, THREADS>>>((const float4*)x, n4, n);
    scan1a<<<1, 1024>>>((long long)n);
    pass1b<<<GRID, THREADS>>>((const float4*)x, n4, n);
    scan1b<<<1, 1024>>>();
    pass2<<<GRID, THREADS>>>((const float4*)x, n4, n);
    scan2a<<<1024, THREADS>>>();
    scan2b<<<1, 1024>>>();
    pass3<<<GRID, THREADS>>>((const float4*)x, (float4*)d_out, n4, n);
}